// round 12
// baseline (speedup 1.0000x reference)
#include <cuda_runtime.h>
#include <cuda_fp16.h>

#define Bb 8
#define Nn 1024
#define Dd 512
#define Hh 8
#define HDIM 64

// ---------------- device scratch (allocation-free rule) ----------------
__device__ __align__(256) __half g_xh[Bb*Nn*Dd];        // x in fp16
__device__ __align__(256) __half g_wh[4*Dd*Dd];         // wq,wk,wv,wo fp16
__device__ __align__(256) __half g_q [Bb*Hh*Nn*HDIM];
__device__ __align__(256) __half g_k [Bb*Hh*Nn*HDIM];
__device__ __align__(256) __half g_vt[Bb*Hh*HDIM*Nn];   // [B,H,hd,N] plain transpose
__device__ __align__(256) __half g_c [Bb*Nn*Dd];        // attention context fp16
__device__ __align__(256) float  g_y [Bb*Nn*Dd];
__device__ __align__(256) unsigned g_adjbits[Bb*Nn*Nn/32];

// ---------------- helpers ----------------
__device__ __forceinline__ void mma_f16(float& c0, float& c1, float& c2, float& c3,
                                        unsigned a0, unsigned a1, unsigned a2, unsigned a3,
                                        unsigned b0, unsigned b1) {
    asm volatile(
        "mma.sync.aligned.m16n8k16.row.col.f32.f16.f16.f32 "
        "{%0,%1,%2,%3},{%4,%5,%6,%7},{%8,%9},{%0,%1,%2,%3};\n"
        : "+f"(c0), "+f"(c1), "+f"(c2), "+f"(c3)
        : "r"(a0), "r"(a1), "r"(a2), "r"(a3), "r"(b0), "r"(b1));
}
// ldmatrix x4: quad = lane>>3 selects (row-octet, col-8-block): v0=(r0-7,c0-7),
// v1=(r8-15,c0-7), v2=(r0-7,c8-15), v3=(r8-15,c8-15) for row-major [r][c] halfs.
__device__ __forceinline__ void ldsm4(unsigned& r0, unsigned& r1, unsigned& r2, unsigned& r3,
                                      unsigned addr) {
    asm volatile("ldmatrix.sync.aligned.m8n8.x4.shared.b16 {%0,%1,%2,%3}, [%4];"
        : "=r"(r0), "=r"(r1), "=r"(r2), "=r"(r3) : "r"(addr));
}
__device__ __forceinline__ void cp16(void* dst_smem, const void* src) {
    unsigned d = (unsigned)__cvta_generic_to_shared(dst_smem);
    asm volatile("cp.async.cg.shared.global [%0], [%1], 16;\n" :: "r"(d), "l"(src));
}
__device__ __forceinline__ void cp_commit() { asm volatile("cp.async.commit_group;\n" ::); }
__device__ __forceinline__ void cp_wait0()  { asm volatile("cp.async.wait_group 0;\n" ::); }
__device__ __forceinline__ unsigned packh2(float lo, float hi) {
    __half2 h = __floats2half2_rn(lo, hi);
    return *(unsigned*)&h;
}

// ---------------- fused prologue: x/w -> fp16, adj -> bitmask ----------------
__global__ void __launch_bounds__(256) prep_kernel(
    const float* __restrict__ x,
    const float* __restrict__ wq, const float* __restrict__ wk,
    const float* __restrict__ wv, const float* __restrict__ wo,
    const int* __restrict__ adj)
{
    const int blk = blockIdx.x;
    const int t   = threadIdx.x;
    if (blk < 4096) {
        const int i = (blk * 256 + t) * 4;
        float4 v = *(const float4*)(x + i);
        uint2 o; o.x = packh2(v.x, v.y); o.y = packh2(v.z, v.w);
        *(uint2*)&g_xh[i] = o;
    } else if (blk < 5120) {
        const int wsel = (blk - 4096) >> 8;
        const float* src = (wsel == 0) ? wq : (wsel == 1) ? wk : (wsel == 2) ? wv : wo;
        const int i = (((blk - 4096) & 255) * 256 + t) * 4;
        float4 v = *(const float4*)(src + i);
        uint2 o; o.x = packh2(v.x, v.y); o.y = packh2(v.z, v.w);
        *(uint2*)&g_wh[wsel * Dd * Dd + i] = o;
    } else {
        const int idx = (blk - 5120) * 256 + t;
        const int4* p = (const int4*)(adj + idx * 32);
        unsigned w = 0;
        #pragma unroll
        for (int j = 0; j < 8; j++) {
            int4 a = p[j];
            w |= (a.x != 0 ? 1u : 0u) << (j * 4 + 0);
            w |= (a.y != 0 ? 1u : 0u) << (j * 4 + 1);
            w |= (a.z != 0 ? 1u : 0u) << (j * 4 + 2);
            w |= (a.w != 0 ? 1u : 0u) << (j * 4 + 3);
        }
        g_adjbits[idx] = w;
    }
}

// ---------------- fp16 GEMM, ldmatrix fragments ----------------
// modes: 0=Q, 1=K, 2=V (plain transposed [B,H,hd,N]), 3=O-proj (+x+bo -> g_y)
// smem row = 64 halfs, stride 36 u32 (144 B): LDSM bank starts 4r mod 32 -> conflict-free.
#define GSTR 36
#define GSTAGEU ((128+64)*GSTR)       // 6912 u32 = 27648 B per stage
__global__ void __launch_bounds__(256, 3) gemm_f16(int mode_p,
    const float* __restrict__ xres, const float* __restrict__ bo)
{
    extern __shared__ unsigned smg[];

    const int mode = (mode_p < 0) ? blockIdx.z : mode_p;
    const __half* __restrict__ A = (mode == 3) ? g_c : g_xh;
    const __half* __restrict__ W = g_wh + mode * Dd * Dd;

    const int m0 = blockIdx.y * 128;
    const int n0 = blockIdx.x * 64;
    const int t  = threadIdx.x;
    const int l  = t & 31;
    const int wid = t >> 5;
    const int wm = wid >> 1;   // 0..3
    const int wn = wid & 1;    // 0..1
    const int quad = l >> 3, lr = l & 7;

    const unsigned smb = (unsigned)__cvta_generic_to_shared(smg);
    const unsigned aBase = smb + ((wm*32 + (quad&1)*8 + lr)*GSTR + (quad>>1)*4) * 4u;
    const unsigned bBase = smb + 128*GSTR*4u + ((wn*32 + (quad&1)*8 + lr)*GSTR + (quad>>1)*4) * 4u;

    float acc[2][4][4];
    #pragma unroll
    for (int mi = 0; mi < 2; mi++)
        #pragma unroll
        for (int ni = 0; ni < 4; ni++)
            #pragma unroll
            for (int c = 0; c < 4; c++) acc[mi][ni][c] = 0.f;

    auto load_stage = [&](int s, int k0) {
        unsigned* sA = smg + s * GSTAGEU;
        unsigned* sB = sA + 128 * GSTR;
        #pragma unroll
        for (int it = 0; it < 4; it++) {
            const int u = t + it * 256;
            const int row = u >> 3;
            const int q   = u & 7;
            cp16(&sA[row * GSTR + q * 4], &A[(m0 + row) * Dd + k0 + q * 8]);
        }
        #pragma unroll
        for (int it = 0; it < 2; it++) {
            const int u = t + it * 256;
            const int row = u >> 3;
            const int q   = u & 7;
            cp16(&sB[row * GSTR + q * 4], &W[(n0 + row) * Dd + k0 + q * 8]);
        }
    };

    load_stage(0, 0);
    cp_commit();

    for (int ki = 0; ki < 8; ki++) {          // K=512, k-tile 64
        cp_wait0();
        __syncthreads();
        if (ki < 7) { load_stage((ki + 1) & 1, (ki + 1) * 64); cp_commit(); }

        const unsigned st = (ki & 1) * (GSTAGEU * 4u);

        #pragma unroll
        for (int ks = 0; ks < 4; ks++) {      // 4 k16-slices
            unsigned af[2][4];
            ldsm4(af[0][0], af[0][1], af[0][2], af[0][3], aBase + st + (ks*8)*4u);
            ldsm4(af[1][0], af[1][1], af[1][2], af[1][3], aBase + st + (16*GSTR + ks*8)*4u);
            #pragma unroll
            for (int j = 0; j < 2; j++) {     // 2 n8-pairs
                unsigned b0, b1, b2, b3;
                ldsm4(b0, b1, b2, b3, bBase + st + (j*16*GSTR + ks*8)*4u);
                #pragma unroll
                for (int mi = 0; mi < 2; mi++) {
                    float* cA = acc[mi][2*j];
                    float* cB = acc[mi][2*j+1];
                    mma_f16(cA[0], cA[1], cA[2], cA[3],
                            af[mi][0], af[mi][1], af[mi][2], af[mi][3], b0, b2);
                    mma_f16(cB[0], cB[1], cB[2], cB[3],
                            af[mi][0], af[mi][1], af[mi][2], af[mi][3], b1, b3);
                }
            }
        }
    }

    // -------- epilogue (genuine C layout: row = base+(l>>2), cols 2(l&3),+1) --------
    if (mode == 0 || mode == 1) {
        __half* O = (mode == 0) ? g_q : g_k;
        const int h = blockIdx.x;
        #pragma unroll
        for (int mi = 0; mi < 2; mi++)
            #pragma unroll
            for (int ni = 0; ni < 4; ni++) {
                const int m  = m0 + wm * 32 + mi * 16 + (l >> 2);
                const int hd = wn * 32 + ni * 8 + 2 * (l & 3);
                const float* c = acc[mi][ni];
                #pragma unroll
                for (int rr = 0; rr < 2; rr++) {
                    const int mr = m + rr * 8;
                    const int b  = mr >> 10;
                    const int n  = mr & 1023;
                    *(unsigned*)&O[(((b * Hh + h) * Nn) + n) * HDIM + hd] =
                        packh2(c[rr * 2 + 0], c[rr * 2 + 1]);
                }
            }
    } else if (mode == 2) {
        // bounce through smem fp32, emit plain transposed [B,H,hd,N]
        __syncthreads();
        float* sf = (float*)smg;   // 128 x 72 floats
        #pragma unroll
        for (int mi = 0; mi < 2; mi++)
            #pragma unroll
            for (int ni = 0; ni < 4; ni++) {
                const int mb = wm * 32 + mi * 16 + (l >> 2);
                const int cc = wn * 32 + ni * 8 + 2 * (l & 3);
                const float* c = acc[mi][ni];
                float2 v0; v0.x = c[0]; v0.y = c[1];
                float2 v1; v1.x = c[2]; v1.y = c[3];
                *(float2*)(sf + mb * 72 + cc)       = v0;
                *(float2*)(sf + (mb + 8) * 72 + cc) = v1;
            }
        __syncthreads();
        const int h = blockIdx.x;
        const int b = m0 >> 10;
        const int ntok0 = m0 & 1023;
        const int hd = t & 63;
        const int tg = t >> 6;          // 0..3 (32 tokens each)
        const int gbase = (((b * Hh + h) * HDIM) + hd) * Nn + ntok0 + tg * 32;
        #pragma unroll
        for (int j = 0; j < 8; j++) {   // 4 tokens per uint2
            float v0 = sf[(tg * 32 + 4*j + 0) * 72 + hd];
            float v1 = sf[(tg * 32 + 4*j + 1) * 72 + hd];
            float v2 = sf[(tg * 32 + 4*j + 2) * 72 + hd];
            float v3 = sf[(tg * 32 + 4*j + 3) * 72 + hd];
            uint2 o; o.x = packh2(v0, v1); o.y = packh2(v2, v3);
            *(uint2*)&g_vt[gbase + 4*j] = o;
        }
    } else {
        // oproj: y = acc + x + bo  -> g_y (fp32)
        #pragma unroll
        for (int mi = 0; mi < 2; mi++)
            #pragma unroll
            for (int ni = 0; ni < 4; ni++) {
                const int m  = m0 + wm * 32 + mi * 16 + (l >> 2);
                const int gc = n0 + wn * 32 + ni * 8 + 2 * (l & 3);
                const float* c = acc[mi][ni];
                float2 bv = *(const float2*)&bo[gc];
                #pragma unroll
                for (int rr = 0; rr < 2; rr++) {
                    const int mr = m + rr * 8;
                    float2 xv = *(const float2*)&xres[mr * Dd + gc];
                    float2 o;
                    o.x = c[rr * 2 + 0] + xv.x + bv.x;
                    o.y = c[rr * 2 + 1] + xv.y + bv.y;
                    *(float2*)&g_y[mr * Dd + gc] = o;
                }
            }
    }
}

// ---------------- flash attention, fp16 mma + ldmatrix, M=32 rows/warp ----------------
// 256 threads, 8 warps x 32 q rows = 256-row Q tile, grid 256. 32-key tiles,
// double-buffered, one barrier/iter. Max-free softmax: p = exp2(s*log2e/8);
// masked -> exp2(-3000) = +0. Score C-frags pack directly into PV k16 A-frags
// (genuine layouts; V^T plain).
#define AQSTR 36                      // Q/K u32 row stride (64 halfs + pad)
#define AVSTR 20                      // V^T u32 row stride (32 halfs + pad); 20r mod 32 distinct
#define AQU (256*AQSTR)               // 9216 u32
#define ASTG (32*AQSTR + 64*AVSTR)    // 2432 u32 per stage
__global__ void __launch_bounds__(256, 2) attn_kernel() {
    extern __shared__ unsigned sma[];

    const int qt = blockIdx.x;   // 0..3
    const int h  = blockIdx.y;
    const int b  = blockIdx.z;
    const int bh = b * Hh + h;
    const int t  = threadIdx.x;
    const int l  = t & 31;
    const int w  = t >> 5;                    // 32 q rows per warp
    const int rq = qt * 256 + w * 32 + (l >> 2);
    const int quad = l >> 3, lr = l & 7;

    const unsigned smb = (unsigned)__cvta_generic_to_shared(sma);
    const unsigned qBase = smb + ((w*32 + (quad&1)*8 + lr)*AQSTR + (quad>>1)*4) * 4u;
    const unsigned kBase = smb + AQU*4u + (((quad&1)*8 + lr)*AQSTR + (quad>>1)*4) * 4u;
    const unsigned vBase = smb + (AQU + 32*AQSTR)*4u + (((quad&1)*8 + lr)*AVSTR + (quad>>1)*4) * 4u;

    // Q tile 256x64 halfs -> smem (async, commit group 0)
    #pragma unroll
    for (int it = 0; it < 8; it++) {
        const int u = t + it * 256;
        const int row = u >> 3;
        const int q   = u & 7;
        cp16(&sma[row * AQSTR + q * 4], &g_q[((bh * Nn) + qt * 256 + row) * HDIM + q * 8]);
    }

    auto load_stage = [&](int s, int kt) {
        unsigned* sK = sma + AQU + s * ASTG;
        unsigned* sV = sK + 32 * AQSTR;
        { // K: 32 rows x 8 chunks = 256 cp16
            const int row = t >> 3;
            const int q   = t & 7;
            cp16(&sK[row * AQSTR + q * 4], &g_k[((bh * Nn) + kt * 32 + row) * HDIM + q * 8]);
        }
        { // V^T: 64 rows x 4 chunks (32 keys = 64B/row) = 256 cp16
            const int row = t >> 2;
            const int q   = t & 3;
            cp16(&sV[row * AVSTR + q * 4], &g_vt[((bh * HDIM) + row) * Nn + kt * 32 + q * 8]);
        }
    };

    load_stage(0, 0);
    cp_commit();

    float o[2][8][4];
    #pragma unroll
    for (int mi = 0; mi < 2; mi++)
        #pragma unroll
        for (int nj = 0; nj < 8; nj++)
            #pragma unroll
            for (int c = 0; c < 4; c++) o[mi][nj][c] = 0.f;
    float lp[2][2] = {{0.f, 0.f}, {0.f, 0.f}};

    const float SC = 0.1803368867f;           // log2(e) / 8

    for (int kt = 0; kt < 32; kt++) {
        cp_wait0();
        __syncthreads();
        if (kt < 31) { load_stage((kt + 1) & 1, kt + 1); cp_commit(); }

        const unsigned st = (kt & 1) * (ASTG * 4u);

        // ---- scores S[32 x 32] per warp ----
        float s[2][4][4];
        #pragma unroll
        for (int mi = 0; mi < 2; mi++)
            #pragma unroll
            for (int ni = 0; ni < 4; ni++)
                #pragma unroll
                for (int c = 0; c < 4; c++) s[mi][ni][c] = 0.f;

        #pragma unroll
        for (int ks = 0; ks < 4; ks++) {      // 4 k16-slices over hd=64
            unsigned af[2][4];
            ldsm4(af[0][0], af[0][1], af[0][2], af[0][3], qBase + (ks*8)*4u);
            ldsm4(af[1][0], af[1][1], af[1][2], af[1][3], qBase + (16*AQSTR + ks*8)*4u);
            #pragma unroll
            for (int j = 0; j < 2; j++) {     // key octet pairs
                unsigned b0, b1, b2, b3;
                ldsm4(b0, b1, b2, b3, kBase + st + (j*16*AQSTR + ks*8)*4u);
                #pragma unroll
                for (int mi = 0; mi < 2; mi++) {
                    float* cA = s[mi][2*j];
                    float* cB = s[mi][2*j+1];
                    mma_f16(cA[0], cA[1], cA[2], cA[3],
                            af[mi][0], af[mi][1], af[mi][2], af[mi][3], b0, b2);
                    mma_f16(cB[0], cB[1], cB[2], cB[3],
                            af[mi][0], af[mi][1], af[mi][2], af[mi][3], b1, b3);
                }
            }
        }

        // ---- mask + scale into log2 domain (masked -> -3000 -> exp2 = +0) ----
        unsigned mw[2][2];
        #pragma unroll
        for (int mi = 0; mi < 2; mi++) {
            mw[mi][0] = g_adjbits[(b * Nn + rq + mi * 16) * (Nn / 32) + kt];
            mw[mi][1] = g_adjbits[(b * Nn + rq + mi * 16 + 8) * (Nn / 32) + kt];
        }
        #pragma unroll
        for (int mi = 0; mi < 2; mi++)
            #pragma unroll
            for (int ni = 0; ni < 4; ni++) {
                const int k0 = ni * 8 + 2 * (l & 3);
                const unsigned b0 = (mw[mi][0] >> k0) & 3u;
                const unsigned b1 = (mw[mi][1] >> k0) & 3u;
                float* c = s[mi][ni];
                c[0] = (b0 & 1u) ? c[0] * SC : -3000.f;
                c[1] = (b0 & 2u) ? c[1] * SC : -3000.f;
                c[2] = (b1 & 1u) ? c[2] * SC : -3000.f;
                c[3] = (b1 & 2u) ? c[3] * SC : -3000.f;
            }

        // ---- P = exp2(s); score C-frags pack into PV k16 A-frags (genuine) ----
        // tile 2g covers keys 0-7 of slice (a0/a1), tile 2g+1 covers keys 8-15 (a2/a3)
        #pragma unroll
        for (int g = 0; g < 2; g++) {
            unsigned pa[2][4];
            #pragma unroll
            for (int mi = 0; mi < 2; mi++) {
                const float pA0 = exp2f(s[mi][2*g][0]);
                const float pA1 = exp2f(s[mi][2*g][1]);
                const float pA2 = exp2f(s[mi][2*g][2]);
                const float pA3 = exp2f(s[mi][2*g][3]);
                const float pB0 = exp2f(s[mi][2*g+1][0]);
                const float pB1 = exp2f(s[mi][2*g+1][1]);
                const float pB2 = exp2f(s[mi][2*g+1][2]);
                const float pB3 = exp2f(s[mi][2*g+1][3]);
                lp[mi][0] += pA0 + pA1 + pB0 + pB1;
                lp[mi][1] += pA2 + pA3 + pB2 + pB3;
                pa[mi][0] = packh2(pA0, pA1);
                pa[mi][1] = packh2(pA2, pA3);
                pa[mi][2] = packh2(pB0, pB1);
                pa[mi][3] = packh2(pB2, pB3);
            }
            #pragma unroll
            for (int jj = 0; jj < 4; jj++) {  // hd octet pairs
                unsigned b0, b1, b2, b3;
                ldsm4(b0, b1, b2, b3, vBase + st + (jj*16*AVSTR + g*8)*4u);
                #pragma unroll
                for (int mi = 0; mi < 2; mi++) {
                    float* cA = o[mi][2*jj];
                    float* cB = o[mi][2*jj+1];
                    mma_f16(cA[0], cA[1], cA[2], cA[3],
                            pa[mi][0], pa[mi][1], pa[mi][2], pa[mi][3], b0, b2);
                    mma_f16(cB[0], cB[1], cB[2], cB[3],
                            pa[mi][0], pa[mi][1], pa[mi][2], pa[mi][3], b1, b3);
                }
            }
        }
    }

    // ---- final row-sum reduction + epilogue (ctx fp16, [B,N,D] head-concat) ----
    #pragma unroll
    for (int mi = 0; mi < 2; mi++) {
        float l0 = lp[mi][0], l1 = lp[mi][1];
        l0 += __shfl_xor_sync(0xffffffffu, l0, 1);
        l0 += __shfl_xor_sync(0xffffffffu, l0, 2);
        l1 += __shfl_xor_sync(0xffffffffu, l1, 1);
        l1 += __shfl_xor_sync(0xffffffffu, l1, 2);
        const float inv0 = 1.f / l0;
        const float inv1 = 1.f / l1;
        const int row0g = b * Nn + rq + mi * 16;
        #pragma unroll
        for (int nj = 0; nj < 8; nj++) {
            const int c = h * HDIM + nj * 8 + 2 * (l & 3);
            const float* oc = o[mi][nj];
            *(unsigned*)&g_c[row0g * Dd + c]       = packh2(oc[0] * inv0, oc[1] * inv0);
            *(unsigned*)&g_c[(row0g + 8) * Dd + c] = packh2(oc[2] * inv1, oc[3] * inv1);
        }
    }
}

// ---------------- LayerNorm over D=512 per row ----------------
__global__ void __launch_bounds__(256) ln_kernel(
    const float* __restrict__ gamma,
    const float* __restrict__ beta,
    float* __restrict__ out)
{
    const int row = blockIdx.x;
    const int t   = threadIdx.x;
    const float* __restrict__ y = g_y + row * Dd;

    float2 v = *(const float2*)&y[t * 2];
    float s = v.x + v.y;
    float q = v.x * v.x + v.y * v.y;
    #pragma unroll
    for (int o = 16; o > 0; o >>= 1) {
        s += __shfl_xor_sync(0xffffffffu, s, o);
        q += __shfl_xor_sync(0xffffffffu, q, o);
    }
    __shared__ float ssum[8], ssq[8];
    if ((t & 31) == 0) { ssum[t >> 5] = s; ssq[t >> 5] = q; }
    __syncthreads();
    float ts = 0.f, tq = 0.f;
    #pragma unroll
    for (int wv = 0; wv < 8; wv++) { ts += ssum[wv]; tq += ssq[wv]; }

    const float mean = ts * (1.f / 512.f);
    const float var  = tq * (1.f / 512.f) - mean * mean;
    const float inv  = rsqrtf(var + 1e-5f);

    float2 g  = *(const float2*)&gamma[t * 2];
    float2 bt = *(const float2*)&beta[t * 2];
    float2 o;
    o.x = (v.x - mean) * inv * g.x + bt.x;
    o.y = (v.y - mean) * inv * g.y + bt.y;
    *(float2*)&out[row * Dd + t * 2] = o;
}

// ---------------------------------------------------------------------------
extern "C" void kernel_launch(void* const* d_in, const int* in_sizes, int n_in,
                              void* d_out, int out_size)
{
    const float* x     = (const float*)d_in[0];
    const int*   adj   = (const int*)  d_in[1];
    const float* wq    = (const float*)d_in[2];
    const float* wk    = (const float*)d_in[3];
    const float* wv    = (const float*)d_in[4];
    const float* wo    = (const float*)d_in[5];
    const float* bo    = (const float*)d_in[6];
    const float* gamma = (const float*)d_in[7];
    const float* beta  = (const float*)d_in[8];
    float* out = (float*)d_out;

    const int gemm_smem = 2 * GSTAGEU * 4;                  // 55296 B
    const int attn_smem = (AQU + 2 * ASTG) * 4;             // 56320 B
    cudaFuncSetAttribute(gemm_f16,   cudaFuncAttributeMaxDynamicSharedMemorySize, gemm_smem);
    cudaFuncSetAttribute(attn_kernel, cudaFuncAttributeMaxDynamicSharedMemorySize, attn_smem);

    prep_kernel<<<6144, 256>>>(x, wq, wk, wv, wo, adj);
    gemm_f16<<<dim3(8, 64, 3), 256, gemm_smem>>>(-1, nullptr, nullptr);
    attn_kernel<<<dim3(4, Hh, Bb), 256, attn_smem>>>();
    gemm_f16<<<dim3(8, 64, 1), 256, gemm_smem>>>(3, x, bo);
    ln_kernel<<<Bb * Nn, 256>>>(gamma, beta, out);
}

// round 13
// speedup vs baseline: 1.1065x; 1.1065x over previous
#include <cuda_runtime.h>
#include <cuda_fp16.h>

#define Bb 8
#define Nn 1024
#define Dd 512
#define Hh 8
#define HDIM 64

// ---------------- device scratch (allocation-free rule) ----------------
__device__ __align__(256) __half g_xh[Bb*Nn*Dd];        // x in fp16
__device__ __align__(256) __half g_wh[4*Dd*Dd];         // wq,wk,wv,wo fp16
__device__ __align__(256) __half g_q [Bb*Hh*Nn*HDIM];
__device__ __align__(256) __half g_k [Bb*Hh*Nn*HDIM];
__device__ __align__(256) __half g_vt[Bb*Hh*HDIM*Nn];   // [B,H,hd,N], keys PERMUTED within 16-groups
__device__ __align__(256) __half g_c [Bb*Nn*Dd];        // attention context fp16
__device__ __align__(256) float  g_y [Bb*Nn*Dd];
__device__ __align__(256) unsigned g_adjbits[Bb*Nn*Nn/32];

// ---------------- helpers ----------------
__device__ __forceinline__ void mma_f16(float& c0, float& c1, float& c2, float& c3,
                                        unsigned a0, unsigned a1, unsigned a2, unsigned a3,
                                        unsigned b0, unsigned b1) {
    asm volatile(
        "mma.sync.aligned.m16n8k16.row.col.f32.f16.f16.f32 "
        "{%0,%1,%2,%3},{%4,%5,%6,%7},{%8,%9},{%0,%1,%2,%3};\n"
        : "+f"(c0), "+f"(c1), "+f"(c2), "+f"(c3)
        : "r"(a0), "r"(a1), "r"(a2), "r"(a3), "r"(b0), "r"(b1));
}
// ldmatrix x4 (GEMM only; attention keeps the measured-faster LDS.64 path)
__device__ __forceinline__ void ldsm4(unsigned& r0, unsigned& r1, unsigned& r2, unsigned& r3,
                                      unsigned addr) {
    asm volatile("ldmatrix.sync.aligned.m8n8.x4.shared.b16 {%0,%1,%2,%3}, [%4];"
        : "=r"(r0), "=r"(r1), "=r"(r2), "=r"(r3) : "r"(addr));
}
__device__ __forceinline__ void cp16(void* dst_smem, const void* src) {
    unsigned d = (unsigned)__cvta_generic_to_shared(dst_smem);
    asm volatile("cp.async.cg.shared.global [%0], [%1], 16;\n" :: "r"(d), "l"(src));
}
__device__ __forceinline__ void cp_commit() { asm volatile("cp.async.commit_group;\n" ::); }
__device__ __forceinline__ void cp_wait0()  { asm volatile("cp.async.wait_group 0;\n" ::); }
__device__ __forceinline__ unsigned packh2(float lo, float hi) {
    __half2 h = __floats2half2_rn(lo, hi);
    return *(unsigned*)&h;
}

// ---------------- fused prologue: x/w -> fp16, adj -> bitmask ----------------
__global__ void __launch_bounds__(256) prep_kernel(
    const float* __restrict__ x,
    const float* __restrict__ wq, const float* __restrict__ wk,
    const float* __restrict__ wv, const float* __restrict__ wo,
    const int* __restrict__ adj)
{
    const int blk = blockIdx.x;
    const int t   = threadIdx.x;
    if (blk < 4096) {
        const int i = (blk * 256 + t) * 4;
        float4 v = *(const float4*)(x + i);
        uint2 o; o.x = packh2(v.x, v.y); o.y = packh2(v.z, v.w);
        *(uint2*)&g_xh[i] = o;
    } else if (blk < 5120) {
        const int wsel = (blk - 4096) >> 8;
        const float* src = (wsel == 0) ? wq : (wsel == 1) ? wk : (wsel == 2) ? wv : wo;
        const int i = (((blk - 4096) & 255) * 256 + t) * 4;
        float4 v = *(const float4*)(src + i);
        uint2 o; o.x = packh2(v.x, v.y); o.y = packh2(v.z, v.w);
        *(uint2*)&g_wh[wsel * Dd * Dd + i] = o;
    } else {
        const int idx = (blk - 5120) * 256 + t;
        const int4* p = (const int4*)(adj + idx * 32);
        unsigned w = 0;
        #pragma unroll
        for (int j = 0; j < 8; j++) {
            int4 a = p[j];
            w |= (a.x != 0 ? 1u : 0u) << (j * 4 + 0);
            w |= (a.y != 0 ? 1u : 0u) << (j * 4 + 1);
            w |= (a.z != 0 ? 1u : 0u) << (j * 4 + 2);
            w |= (a.w != 0 ? 1u : 0u) << (j * 4 + 3);
        }
        g_adjbits[idx] = w;
    }
}

// ---------------- fp16 GEMM, ldmatrix fragments (measured faster in R11) ----------------
// modes: 0=Q, 1=K, 2=V (transposed + key-permuted [B,H,hd,N]), 3=O-proj (+x+bo -> g_y)
// smem row = 64 halfs, stride 36 u32 (144 B).
#define GSTR 36
#define GSTAGEU ((128+64)*GSTR)       // 6912 u32 = 27648 B per stage
__global__ void __launch_bounds__(256, 3) gemm_f16(int mode_p,
    const float* __restrict__ xres, const float* __restrict__ bo)
{
    extern __shared__ unsigned smg[];

    const int mode = (mode_p < 0) ? blockIdx.z : mode_p;
    const __half* __restrict__ A = (mode == 3) ? g_c : g_xh;
    const __half* __restrict__ W = g_wh + mode * Dd * Dd;

    const int m0 = blockIdx.y * 128;
    const int n0 = blockIdx.x * 64;
    const int t  = threadIdx.x;
    const int l  = t & 31;
    const int wid = t >> 5;
    const int wm = wid >> 1;   // 0..3
    const int wn = wid & 1;    // 0..1
    const int quad = l >> 3, lr = l & 7;

    const unsigned smb = (unsigned)__cvta_generic_to_shared(smg);
    const unsigned aBase = smb + ((wm*32 + (quad&1)*8 + lr)*GSTR + (quad>>1)*4) * 4u;
    const unsigned bBase = smb + 128*GSTR*4u + ((wn*32 + (quad&1)*8 + lr)*GSTR + (quad>>1)*4) * 4u;

    float acc[2][4][4];
    #pragma unroll
    for (int mi = 0; mi < 2; mi++)
        #pragma unroll
        for (int ni = 0; ni < 4; ni++)
            #pragma unroll
            for (int c = 0; c < 4; c++) acc[mi][ni][c] = 0.f;

    auto load_stage = [&](int s, int k0) {
        unsigned* sA = smg + s * GSTAGEU;
        unsigned* sB = sA + 128 * GSTR;
        #pragma unroll
        for (int it = 0; it < 4; it++) {
            const int u = t + it * 256;
            const int row = u >> 3;
            const int q   = u & 7;
            cp16(&sA[row * GSTR + q * 4], &A[(m0 + row) * Dd + k0 + q * 8]);
        }
        #pragma unroll
        for (int it = 0; it < 2; it++) {
            const int u = t + it * 256;
            const int row = u >> 3;
            const int q   = u & 7;
            cp16(&sB[row * GSTR + q * 4], &W[(n0 + row) * Dd + k0 + q * 8]);
        }
    };

    load_stage(0, 0);
    cp_commit();

    for (int ki = 0; ki < 8; ki++) {          // K=512, k-tile 64
        cp_wait0();
        __syncthreads();
        if (ki < 7) { load_stage((ki + 1) & 1, (ki + 1) * 64); cp_commit(); }

        const unsigned st = (ki & 1) * (GSTAGEU * 4u);

        #pragma unroll
        for (int ks = 0; ks < 4; ks++) {      // 4 k16-slices
            unsigned af[2][4];
            ldsm4(af[0][0], af[0][1], af[0][2], af[0][3], aBase + st + (ks*8)*4u);
            ldsm4(af[1][0], af[1][1], af[1][2], af[1][3], aBase + st + (16*GSTR + ks*8)*4u);
            #pragma unroll
            for (int j = 0; j < 2; j++) {     // 2 n8-pairs
                unsigned b0, b1, b2, b3;
                ldsm4(b0, b1, b2, b3, bBase + st + (j*16*GSTR + ks*8)*4u);
                #pragma unroll
                for (int mi = 0; mi < 2; mi++) {
                    float* cA = acc[mi][2*j];
                    float* cB = acc[mi][2*j+1];
                    mma_f16(cA[0], cA[1], cA[2], cA[3],
                            af[mi][0], af[mi][1], af[mi][2], af[mi][3], b0, b2);
                    mma_f16(cB[0], cB[1], cB[2], cB[3],
                            af[mi][0], af[mi][1], af[mi][2], af[mi][3], b1, b3);
                }
            }
        }
    }

    // -------- epilogue (C layout: row = base+(l>>2), cols 2(l&3),+1) --------
    if (mode == 0 || mode == 1) {
        __half* O = (mode == 0) ? g_q : g_k;
        const int h = blockIdx.x;
        #pragma unroll
        for (int mi = 0; mi < 2; mi++)
            #pragma unroll
            for (int ni = 0; ni < 4; ni++) {
                const int m  = m0 + wm * 32 + mi * 16 + (l >> 2);
                const int hd = wn * 32 + ni * 8 + 2 * (l & 3);
                const float* c = acc[mi][ni];
                #pragma unroll
                for (int rr = 0; rr < 2; rr++) {
                    const int mr = m + rr * 8;
                    const int b  = mr >> 10;
                    const int n  = mr & 1023;
                    *(unsigned*)&O[(((b * Hh + h) * Nn) + n) * HDIM + hd] =
                        packh2(c[rr * 2 + 0], c[rr * 2 + 1]);
                }
            }
    } else if (mode == 2) {
        // bounce through smem fp32, emit transposed [B,H,hd,N] with the R10 key perm:
        // within each 16-token group, pos 4j <- tokens (2j,2j+1), pos 4j+2 <- (8+2j,8+2j+1)
        __syncthreads();
        float* sf = (float*)smg;   // 128 x 72 floats
        #pragma unroll
        for (int mi = 0; mi < 2; mi++)
            #pragma unroll
            for (int ni = 0; ni < 4; ni++) {
                const int mb = wm * 32 + mi * 16 + (l >> 2);
                const int cc = wn * 32 + ni * 8 + 2 * (l & 3);
                const float* c = acc[mi][ni];
                float2 v0; v0.x = c[0]; v0.y = c[1];
                float2 v1; v1.x = c[2]; v1.y = c[3];
                *(float2*)(sf + mb * 72 + cc)       = v0;
                *(float2*)(sf + (mb + 8) * 72 + cc) = v1;
            }
        __syncthreads();
        const int h = blockIdx.x;
        const int b = m0 >> 10;
        const int ntok0 = m0 & 1023;
        const int hd = t & 63;
        const int tg = t >> 6;          // 0..3 (32 tokens each)
        const int gbase = (((b * Hh + h) * HDIM) + hd) * Nn + ntok0 + tg * 32;
        #pragma unroll
        for (int grp = 0; grp < 2; grp++) {
            const int tb = tg * 32 + grp * 16;
            #pragma unroll
            for (int j = 0; j < 4; j++) {
                float v0 = sf[(tb + 2*j    ) * 72 + hd];
                float v1 = sf[(tb + 2*j + 1) * 72 + hd];
                float v2 = sf[(tb + 8 + 2*j    ) * 72 + hd];
                float v3 = sf[(tb + 8 + 2*j + 1) * 72 + hd];
                *(unsigned*)&g_vt[gbase + grp * 16 + 4*j    ] = packh2(v0, v1);
                *(unsigned*)&g_vt[gbase + grp * 16 + 4*j + 2] = packh2(v2, v3);
            }
        }
    } else {
        // oproj: y = acc + x + bo  -> g_y (fp32)
        #pragma unroll
        for (int mi = 0; mi < 2; mi++)
            #pragma unroll
            for (int ni = 0; ni < 4; ni++) {
                const int m  = m0 + wm * 32 + mi * 16 + (l >> 2);
                const int gc = n0 + wn * 32 + ni * 8 + 2 * (l & 3);
                const float* c = acc[mi][ni];
                float2 bv = *(const float2*)&bo[gc];
                #pragma unroll
                for (int rr = 0; rr < 2; rr++) {
                    const int mr = m + rr * 8;
                    float2 xv = *(const float2*)&xres[mr * Dd + gc];
                    float2 o;
                    o.x = c[rr * 2 + 0] + xv.x + bv.x;
                    o.y = c[rr * 2 + 1] + xv.y + bv.y;
                    *(float2*)&g_y[mr * Dd + gc] = o;
                }
            }
    }
}

// ---------------- flash attention (R10 version, verbatim): fp16 mma, LDS.64 + k-perm ----------------
#define QSU 40                        // Q/K u32 row stride (64 halfs + pad)
#define VSU 24                        // V^T u32 row stride (32 halfs + pad)
#define ASTAGEU (32*QSU + 64*VSU)     // 2816 u32 per stage
#define AQFU (256*QSU)                // 10240 u32
__global__ void __launch_bounds__(256, 2) attn_kernel() {
    extern __shared__ unsigned sma[];
    unsigned* sQ = sma;                       // 256 x 40 u32

    const int qt = blockIdx.x;   // 0..3
    const int h  = blockIdx.y;
    const int b  = blockIdx.z;
    const int bh = b * Hh + h;
    const int t  = threadIdx.x;
    const int l  = t & 31;
    const int w  = t >> 5;                    // 32 q rows per warp
    const int rq = qt * 256 + w * 32 + (l >> 2);

    // Q tile 256x64 halfs -> smem (async, commit group 0)
    #pragma unroll
    for (int it = 0; it < 8; it++) {
        const int u = t + it * 256;
        const int row = u >> 3;
        const int q   = u & 7;
        cp16(&sQ[row * QSU + q * 4], &g_q[((bh * Nn) + qt * 256 + row) * HDIM + q * 8]);
    }

    auto load_stage = [&](int s, int kt) {
        unsigned* sK = sma + AQFU + s * ASTAGEU;
        unsigned* sV = sK + 32 * QSU;
        { // K: 32 rows x 8 chunks = 256 cp16
            const int row = t >> 3;
            const int q   = t & 7;
            cp16(&sK[row * QSU + q * 4], &g_k[((bh * Nn) + kt * 32 + row) * HDIM + q * 8]);
        }
        { // V^T: 64 rows x 4 chunks of 16B (32 keys = 64B/row) = 256 cp16
            const int row = t >> 2;
            const int q   = t & 3;
            cp16(&sV[row * VSU + q * 4], &g_vt[((bh * HDIM) + row) * Nn + kt * 32 + q * 8]);
        }
    };

    load_stage(0, 0);
    cp_commit();

    float o[2][8][4];
    #pragma unroll
    for (int mi = 0; mi < 2; mi++)
        #pragma unroll
        for (int nj = 0; nj < 8; nj++)
            #pragma unroll
            for (int c = 0; c < 4; c++) o[mi][nj][c] = 0.f;
    float lp[2][2] = {{0.f, 0.f}, {0.f, 0.f}};

    const float SC = 0.1803368867f;           // log2(e) / 8

    for (int kt = 0; kt < 32; kt++) {
        cp_wait0();
        __syncthreads();
        if (kt < 31) { load_stage((kt + 1) & 1, kt + 1); cp_commit(); }

        const unsigned* sK = sma + AQFU + (kt & 1) * ASTAGEU;
        const unsigned* sV = sK + 32 * QSU;

        // ---- scores S[32 x 32] per warp (2 m16 tiles, 4 n8 tiles) ----
        float s[2][4][4];
        #pragma unroll
        for (int mi = 0; mi < 2; mi++)
            #pragma unroll
            for (int ni = 0; ni < 4; ni++)
                #pragma unroll
                for (int c = 0; c < 4; c++) s[mi][ni][c] = 0.f;

        #pragma unroll
        for (int ks = 0; ks < 4; ks++) {      // 4 k16-slices over hd=64
            const int kc = ks * 8 + 2 * (l & 3);
            unsigned af[2][4];
            #pragma unroll
            for (int mi = 0; mi < 2; mi++) {
                const int rb = w * 32 + mi * 16 + (l >> 2);
                uint2 r0 = *(const uint2*)(sQ + rb * QSU + kc);
                uint2 r8 = *(const uint2*)(sQ + (rb + 8) * QSU + kc);
                af[mi][0] = r0.x; af[mi][1] = r8.x; af[mi][2] = r0.y; af[mi][3] = r8.y;
            }
            #pragma unroll
            for (int ni = 0; ni < 4; ni++) {
                uint2 bv = *(const uint2*)(sK + (ni * 8 + (l >> 2)) * QSU + kc);
                #pragma unroll
                for (int mi = 0; mi < 2; mi++) {
                    float* c = s[mi][ni];
                    mma_f16(c[0], c[1], c[2], c[3],
                            af[mi][0], af[mi][1], af[mi][2], af[mi][3], bv.x, bv.y);
                }
            }
        }

        // ---- mask + scale into log2 domain (masked -> -3000 -> exp2 = +0) ----
        unsigned mw[2][2];
        #pragma unroll
        for (int mi = 0; mi < 2; mi++) {
            mw[mi][0] = g_adjbits[(b * Nn + rq + mi * 16) * (Nn / 32) + kt];
            mw[mi][1] = g_adjbits[(b * Nn + rq + mi * 16 + 8) * (Nn / 32) + kt];
        }
        #pragma unroll
        for (int mi = 0; mi < 2; mi++)
            #pragma unroll
            for (int ni = 0; ni < 4; ni++) {
                const int k0 = ni * 8 + 2 * (l & 3);
                const unsigned b0 = (mw[mi][0] >> k0) & 3u;
                const unsigned b1 = (mw[mi][1] >> k0) & 3u;
                float* c = s[mi][ni];
                c[0] = (b0 & 1u) ? c[0] * SC : -3000.f;
                c[1] = (b0 & 2u) ? c[1] * SC : -3000.f;
                c[2] = (b1 & 1u) ? c[2] * SC : -3000.f;
                c[3] = (b1 & 2u) ? c[3] * SC : -3000.f;
            }

        // ---- P = exp2(s); pack score C-frags into PV k16 A-frags ----
        #pragma unroll
        for (int g = 0; g < 2; g++) {
            unsigned pa[2][4];
            #pragma unroll
            for (int mi = 0; mi < 2; mi++) {
                const float pA0 = exp2f(s[mi][2*g][0]);
                const float pA1 = exp2f(s[mi][2*g][1]);
                const float pA2 = exp2f(s[mi][2*g][2]);
                const float pA3 = exp2f(s[mi][2*g][3]);
                const float pB0 = exp2f(s[mi][2*g+1][0]);
                const float pB1 = exp2f(s[mi][2*g+1][1]);
                const float pB2 = exp2f(s[mi][2*g+1][2]);
                const float pB3 = exp2f(s[mi][2*g+1][3]);
                lp[mi][0] += pA0 + pA1 + pB0 + pB1;
                lp[mi][1] += pA2 + pA3 + pB2 + pB3;
                pa[mi][0] = packh2(pA0, pA1);
                pa[mi][1] = packh2(pA2, pA3);
                pa[mi][2] = packh2(pB0, pB1);
                pa[mi][3] = packh2(pB2, pB3);
            }
            const int kc = g * 8 + 2 * (l & 3);
            #pragma unroll
            for (int nj = 0; nj < 8; nj++) {
                uint2 bv = *(const uint2*)(sV + (nj * 8 + (l >> 2)) * VSU + kc);
                #pragma unroll
                for (int mi = 0; mi < 2; mi++) {
                    float* c = o[mi][nj];
                    mma_f16(c[0], c[1], c[2], c[3],
                            pa[mi][0], pa[mi][1], pa[mi][2], pa[mi][3], bv.x, bv.y);
                }
            }
        }
    }

    // ---- final row-sum reduction + epilogue (ctx fp16, [B,N,D] head-concat) ----
    #pragma unroll
    for (int mi = 0; mi < 2; mi++) {
        float l0 = lp[mi][0], l1 = lp[mi][1];
        l0 += __shfl_xor_sync(0xffffffffu, l0, 1);
        l0 += __shfl_xor_sync(0xffffffffu, l0, 2);
        l1 += __shfl_xor_sync(0xffffffffu, l1, 1);
        l1 += __shfl_xor_sync(0xffffffffu, l1, 2);
        const float inv0 = 1.f / l0;
        const float inv1 = 1.f / l1;
        const int row0g = b * Nn + rq + mi * 16;
        #pragma unroll
        for (int nj = 0; nj < 8; nj++) {
            const int c = h * HDIM + nj * 8 + 2 * (l & 3);
            const float* oc = o[mi][nj];
            *(unsigned*)&g_c[row0g * Dd + c]       = packh2(oc[0] * inv0, oc[1] * inv0);
            *(unsigned*)&g_c[(row0g + 8) * Dd + c] = packh2(oc[2] * inv1, oc[3] * inv1);
        }
    }
}

// ---------------- LayerNorm over D=512 per row ----------------
__global__ void __launch_bounds__(256) ln_kernel(
    const float* __restrict__ gamma,
    const float* __restrict__ beta,
    float* __restrict__ out)
{
    const int row = blockIdx.x;
    const int t   = threadIdx.x;
    const float* __restrict__ y = g_y + row * Dd;

    float2 v = *(const float2*)&y[t * 2];
    float s = v.x + v.y;
    float q = v.x * v.x + v.y * v.y;
    #pragma unroll
    for (int o = 16; o > 0; o >>= 1) {
        s += __shfl_xor_sync(0xffffffffu, s, o);
        q += __shfl_xor_sync(0xffffffffu, q, o);
    }
    __shared__ float ssum[8], ssq[8];
    if ((t & 31) == 0) { ssum[t >> 5] = s; ssq[t >> 5] = q; }
    __syncthreads();
    float ts = 0.f, tq = 0.f;
    #pragma unroll
    for (int wv = 0; wv < 8; wv++) { ts += ssum[wv]; tq += ssq[wv]; }

    const float mean = ts * (1.f / 512.f);
    const float var  = tq * (1.f / 512.f) - mean * mean;
    const float inv  = rsqrtf(var + 1e-5f);

    float2 g  = *(const float2*)&gamma[t * 2];
    float2 bt = *(const float2*)&beta[t * 2];
    float2 o;
    o.x = (v.x - mean) * inv * g.x + bt.x;
    o.y = (v.y - mean) * inv * g.y + bt.y;
    *(float2*)&out[row * Dd + t * 2] = o;
}

// ---------------------------------------------------------------------------
extern "C" void kernel_launch(void* const* d_in, const int* in_sizes, int n_in,
                              void* d_out, int out_size)
{
    const float* x     = (const float*)d_in[0];
    const int*   adj   = (const int*)  d_in[1];
    const float* wq    = (const float*)d_in[2];
    const float* wk    = (const float*)d_in[3];
    const float* wv    = (const float*)d_in[4];
    const float* wo    = (const float*)d_in[5];
    const float* bo    = (const float*)d_in[6];
    const float* gamma = (const float*)d_in[7];
    const float* beta  = (const float*)d_in[8];
    float* out = (float*)d_out;

    const int gemm_smem = 2 * GSTAGEU * 4;                  // 55296 B
    const int attn_smem = (AQFU + 2 * ASTAGEU) * 4;         // 63488 B
    cudaFuncSetAttribute(gemm_f16,   cudaFuncAttributeMaxDynamicSharedMemorySize, gemm_smem);
    cudaFuncSetAttribute(attn_kernel, cudaFuncAttributeMaxDynamicSharedMemorySize, attn_smem);

    prep_kernel<<<6144, 256>>>(x, wq, wk, wv, wo, adj);
    gemm_f16<<<dim3(8, 64, 3), 256, gemm_smem>>>(-1, nullptr, nullptr);
    attn_kernel<<<dim3(4, Hh, Bb), 256, attn_smem>>>();
    gemm_f16<<<dim3(8, 64, 1), 256, gemm_smem>>>(3, x, bo);
    ln_kernel<<<Bb * Nn, 256>>>(gamma, beta, out);
}